// round 1
// baseline (speedup 1.0000x reference)
#include <cuda_runtime.h>
#include <math.h>

#define B_  16
#define L_  2048
#define D_  512
#define E_  8
#define H_  8
#define HD_ 64
#define EH_ 64
#define F_  2048

typedef unsigned long long ull;

// ---------------- scratch (static device globals; no allocation) ----------------
__device__ __align__(16) float g_xn[B_*D_];
__device__ __align__(16) float g_gates[B_*E_];
__device__ __align__(16) float g_qh[B_*E_*D_];
__device__ __align__(16) float g_wt[B_*EH_*D_];        // (1/8) * qh_h . Wk_h^T
__device__ __align__(16) float g_sc[B_*EH_*L_];        // scores, then probs in-place
__device__ __align__(16) float g_ctxp[2][B_*EH_*D_];   // ctx k-split partials
__device__ __align__(16) float g_attn[B_*E_*D_];
__device__ __align__(16) float g_x[B_*E_*D_];
__device__ __align__(16) float g_xo[B_*E_*D_];
__device__ __align__(16) float g_h1[B_*E_*F_];
__device__ __align__(16) float g_rel[B_*E_];

// ---------------- f32x2 packed FMA helpers ----------------
__device__ __forceinline__ ull pack2(float lo, float hi){
    ull u; asm("mov.b64 %0,{%1,%2};" : "=l"(u) : "f"(lo), "f"(hi)); return u;
}
__device__ __forceinline__ float2 unpack2(ull u){
    float2 r; asm("mov.b64 {%0,%1},%2;" : "=f"(r.x), "=f"(r.y) : "l"(u)); return r;
}
#define FMA2(d,a,b) asm("fma.rn.f32x2 %0,%1,%2,%0;" : "+l"(d) : "l"(a), "l"(b))

__device__ __forceinline__ float blockReduceSum(float v, float* red){
    int t = threadIdx.x;
    red[t] = v; __syncthreads();
    #pragma unroll
    for (int s = 128; s > 0; s >>= 1){ if (t < s) red[t] += red[t+s]; __syncthreads(); }
    float r = red[0]; __syncthreads(); return r;
}

// ---------------- k1: query LN stats + gating softmax ----------------
__global__ void k_prep(const float* __restrict__ q, const float* __restrict__ wg){
    int b = blockIdx.x, t = threadIdx.x;
    __shared__ float red[256];
    __shared__ float slog[8];
    float s = 0.f;
    for (int d = t; d < D_; d += 256) s += q[b*D_+d];
    float mu = blockReduceSum(s, red) * (1.f/512.f);
    float v = 0.f;
    for (int d = t; d < D_; d += 256){ float x = q[b*D_+d]-mu; v += x*x; }
    float var = blockReduceSum(v, red) * (1.f/512.f);
    float rs = rsqrtf(var + 1e-5f);
    for (int d = t; d < D_; d += 256) g_xn[b*D_+d] = (q[b*D_+d]-mu)*rs;
    // gates: one warp per expert
    int w = t >> 5, lane = t & 31;
    float p = 0.f;
    for (int d = lane; d < D_; d += 32) p += q[b*D_+d] * wg[d*E_ + w];
    #pragma unroll
    for (int o = 16; o > 0; o >>= 1) p += __shfl_xor_sync(0xffffffffu, p, o);
    if (lane == 0) slog[w] = p;
    __syncthreads();
    if (t == 0){
        float m = slog[0];
        #pragma unroll
        for (int e = 1; e < 8; e++) m = fmaxf(m, slog[e]);
        float z = 0.f, ex[8];
        #pragma unroll
        for (int e = 0; e < 8; e++){ ex[e] = expf(slog[e]-m); z += ex[e]; }
        float iz = 1.f/z;
        #pragma unroll
        for (int e = 0; e < 8; e++) g_gates[b*8+e] = ex[e]*iz;
    }
}

// ---------------- k2: qh = qn @ Wq + bq  (per-expert affine LN applied on load) ----------------
__global__ void k_qh(const float* __restrict__ Wq, const float* __restrict__ bq,
                     const float* __restrict__ lng, const float* __restrict__ lnb){
    int e = blockIdx.x >> 2, kt = blockIdx.x & 3;
    int t = threadIdx.x;
    __shared__ float sQ[16*512];
    for (int i = t; i < 8192; i += 256){
        int b = i >> 9, d = i & 511;
        sQ[i] = g_xn[b*512+d]*lng[e*512+d] + lnb[e*512+d];
    }
    __syncthreads();
    int col = kt*128 + (t & 127);
    int bg = t >> 7;
    float acc[8] = {0,0,0,0,0,0,0,0};
    const float* W = Wq + e*262144 + col;
    for (int d = 0; d < 512; d++){
        float w = W[d*512];
        #pragma unroll
        for (int j = 0; j < 8; j++) acc[j] += sQ[(bg*8+j)*512+d]*w;
    }
    float bb = bq[e*512+col];
    #pragma unroll
    for (int j = 0; j < 8; j++){
        int b = bg*8+j;
        g_qh[(b*8+e)*512+col] = acc[j] + bb;
    }
}

// ---------------- k3: w_tilde[b,eh,din] = (1/8) sum_c qh[b,e,h*64+c] * Wk[e][din][h*64+c] ----------------
__global__ void k_wt(const float* __restrict__ Wk){
    int e = blockIdx.x >> 3, dt = blockIdx.x & 7;
    int din0 = dt*64;
    int t = threadIdx.x;
    __shared__ float qhS[16*64];
    __shared__ float wkS[64*65];
    int r = t & 63, bg = t >> 6;
    for (int h = 0; h < 8; h++){
        __syncthreads();
        for (int i = t; i < 1024; i += 256){
            int b = i >> 6, c = i & 63;
            qhS[i] = g_qh[(b*8+e)*512 + h*64 + c];
        }
        for (int i = t; i < 4096; i += 256){
            int rr = i >> 6, c = i & 63;
            wkS[rr*65+c] = Wk[e*262144 + (din0+rr)*512 + h*64 + c];
        }
        __syncthreads();
        #pragma unroll
        for (int j = 0; j < 4; j++){
            int b = bg*4 + j;
            float a = 0.f;
            const float* qp = &qhS[b*64];
            const float* wp = &wkS[r*65];
            #pragma unroll 8
            for (int c = 0; c < 64; c++) a += qp[c]*wp[c];
            g_wt[((b*64) + (e*8+h))*512 + din0 + r] = a * 0.125f;
        }
    }
}

// ---------------- k4: scores[b,eh,l] = sum_d r[b,l,d] * wt[b,eh,d]  (NT gemm, f32x2) ----------------
__global__ void k_scores(const float* __restrict__ R){
    int b = blockIdx.x >> 4, lt = blockIdx.x & 15;
    int l0 = lt*128;
    int t = threadIdx.x, tx = t & 15, ty = t >> 4;
    __shared__ __align__(16) float RsT[32*128];
    __shared__ __align__(16) float WsT[32*64];
    ull acc[4][4];
    #pragma unroll
    for (int i = 0; i < 4; i++)
        #pragma unroll
        for (int j = 0; j < 4; j++) acc[i][j] = 0ull;

    for (int kc = 0; kc < 16; kc++){
        __syncthreads();
        #pragma unroll
        for (int it = 0; it < 4; it++){
            int idx = it*256 + t; int row = idx >> 3, c4 = idx & 7;
            float4 v = *(const float4*)&R[((b*2048)+(l0+row))*512 + kc*32 + c4*4];
            RsT[(c4*4+0)*128+row] = v.x; RsT[(c4*4+1)*128+row] = v.y;
            RsT[(c4*4+2)*128+row] = v.z; RsT[(c4*4+3)*128+row] = v.w;
        }
        #pragma unroll
        for (int it = 0; it < 2; it++){
            int idx = it*256 + t; int eh = idx >> 3, c4 = idx & 7;
            float4 v = *(const float4*)&g_wt[((b*64)+eh)*512 + kc*32 + c4*4];
            WsT[(c4*4+0)*64+eh] = v.x; WsT[(c4*4+1)*64+eh] = v.y;
            WsT[(c4*4+2)*64+eh] = v.z; WsT[(c4*4+3)*64+eh] = v.w;
        }
        __syncthreads();
        #pragma unroll 8
        for (int kk = 0; kk < 32; kk++){
            const ull* ap = (const ull*)&RsT[kk*128 + tx*8];
            ull a0 = ap[0], a1 = ap[1], a2 = ap[2], a3 = ap[3];
            float4 b4 = *(const float4*)&WsT[kk*64 + ty*4];
            ull bb0 = pack2(b4.x,b4.x), bb1 = pack2(b4.y,b4.y);
            ull bb2 = pack2(b4.z,b4.z), bb3 = pack2(b4.w,b4.w);
            FMA2(acc[0][0],a0,bb0); FMA2(acc[0][1],a0,bb1); FMA2(acc[0][2],a0,bb2); FMA2(acc[0][3],a0,bb3);
            FMA2(acc[1][0],a1,bb0); FMA2(acc[1][1],a1,bb1); FMA2(acc[1][2],a1,bb2); FMA2(acc[1][3],a1,bb3);
            FMA2(acc[2][0],a2,bb0); FMA2(acc[2][1],a2,bb1); FMA2(acc[2][2],a2,bb2); FMA2(acc[2][3],a2,bb3);
            FMA2(acc[3][0],a3,bb0); FMA2(acc[3][1],a3,bb1); FMA2(acc[3][2],a3,bb2); FMA2(acc[3][3],a3,bb3);
        }
    }
    #pragma unroll
    for (int j = 0; j < 4; j++){
        float2 p0 = unpack2(acc[0][j]), p1 = unpack2(acc[1][j]);
        float2 p2 = unpack2(acc[2][j]), p3 = unpack2(acc[3][j]);
        float* out = &g_sc[((b*64)+(ty*4+j))*2048 + l0 + tx*8];
        *(float4*)out     = make_float4(p0.x,p0.y,p1.x,p1.y);
        *(float4*)(out+4) = make_float4(p2.x,p2.y,p3.x,p3.y);
    }
}

// ---------------- k5: softmax per (b,e,h) row, probs in-place, head-avg entropy -> rel ----------------
__global__ void k_soft(){
    int b = blockIdx.x >> 3, e = blockIdx.x & 7;
    int t = threadIdx.x, w = t >> 5, lane = t & 31;
    __shared__ float sm[8], sz[8];
    __shared__ float red[256];
    float* base = g_sc + ((b*64)+(e*8))*2048;
    {
        float m = -1e30f;
        const float* row = base + w*2048;
        for (int l = lane; l < 2048; l += 32) m = fmaxf(m, row[l]);
        #pragma unroll
        for (int o = 16; o > 0; o >>= 1) m = fmaxf(m, __shfl_xor_sync(0xffffffffu, m, o));
        if (lane == 0) sm[w] = m;
    }
    __syncthreads();
    {
        float z = 0.f; float m = sm[w];
        const float* row = base + w*2048;
        for (int l = lane; l < 2048; l += 32) z += expf(row[l]-m);
        #pragma unroll
        for (int o = 16; o > 0; o >>= 1) z += __shfl_xor_sync(0xffffffffu, z, o);
        if (lane == 0) sz[w] = z;
    }
    __syncthreads();
    float mh[8], izh[8];
    #pragma unroll
    for (int h = 0; h < 8; h++){ mh[h] = sm[h]; izh[h] = 1.f/sz[h]; }
    float ent = 0.f;
    for (int l = t; l < 2048; l += 256){
        float pbar = 0.f;
        #pragma unroll
        for (int h = 0; h < 8; h++){
            float p = expf(base[h*2048+l]-mh[h])*izh[h];
            base[h*2048+l] = p;
            pbar += p;
        }
        pbar *= 0.125f;
        ent -= pbar * logf(fmaxf(pbar, 1e-12f));
    }
    float Hn = blockReduceSum(ent, red);
    if (t == 0){
        float sa = expf(-0.5f*Hn);
        g_rel[b*8+e] = g_gates[b*8+e]*sa;
    }
}

// ---------------- k6: ctx[b,eh,d] = sum_l probs[b,eh,l] * r[b,l,d]  (k-split x2, f32x2) ----------------
__global__ void k_ctx(const float* __restrict__ R){
    int id = blockIdx.x;
    int b = id >> 4; int r2 = id & 15; int dt = r2 >> 1, ks = r2 & 1;
    int d0 = dt*64, lbase = ks*1024;
    int t = threadIdx.x, tx = t & 15, ty = t >> 4;
    __shared__ __align__(16) float Ps[64*33];
    __shared__ __align__(16) float Rs[32*64];
    ull acc[4][2];
    #pragma unroll
    for (int i = 0; i < 4; i++){ acc[i][0] = 0ull; acc[i][1] = 0ull; }

    for (int kc = 0; kc < 32; kc++){
        __syncthreads();
        #pragma unroll
        for (int it = 0; it < 2; it++){
            int idx = it*256 + t; int eh = idx >> 3, c4 = idx & 7;
            float4 v = *(const float4*)&g_sc[((b*64)+eh)*2048 + lbase + kc*32 + c4*4];
            Ps[eh*33+c4*4+0] = v.x; Ps[eh*33+c4*4+1] = v.y;
            Ps[eh*33+c4*4+2] = v.z; Ps[eh*33+c4*4+3] = v.w;
        }
        #pragma unroll
        for (int it = 0; it < 2; it++){
            int idx = it*256 + t; int ll = idx >> 4, d4 = idx & 15;
            *(float4*)&Rs[ll*64 + d4*4] =
                *(const float4*)&R[((b*2048)+lbase+kc*32+ll)*512 + d0 + d4*4];
        }
        __syncthreads();
        #pragma unroll 8
        for (int kk = 0; kk < 32; kk++){
            ulonglong2 bb = *(const ulonglong2*)&Rs[kk*64 + tx*4];
            #pragma unroll
            for (int i = 0; i < 4; i++){
                float a = Ps[(ty*4+i)*33 + kk];
                ull a2 = pack2(a,a);
                FMA2(acc[i][0], a2, bb.x);
                FMA2(acc[i][1], a2, bb.y);
            }
        }
    }
    #pragma unroll
    for (int i = 0; i < 4; i++){
        float2 q0 = unpack2(acc[i][0]), q1 = unpack2(acc[i][1]);
        *(float4*)&g_ctxp[ks][((b*64)+(ty*4+i))*512 + d0 + tx*4] =
            make_float4(q0.x,q0.y,q1.x,q1.y);
    }
}

// ---------------- k7: attn[b, e, h*64+c] = ctx[b,eh,:] @ Wv[e][:, h*64+c] + bv ----------------
__global__ void k_attn(const float* __restrict__ Wv, const float* __restrict__ bv){
    int e = blockIdx.x >> 3, h = blockIdx.x & 7;
    int t = threadIdx.x;
    __shared__ float cS[16*512];
    for (int i = t; i < 8192; i += 256){
        int b = i >> 9, d = i & 511;
        int row = (b*64) + (e*8+h);
        cS[i] = g_ctxp[0][row*512+d] + g_ctxp[1][row*512+d];
    }
    __syncthreads();
    int c = t & 63, bg = t >> 6;
    float acc[4] = {0,0,0,0};
    const float* W = Wv + e*262144 + h*64 + c;
    for (int d = 0; d < 512; d++){
        float w = W[d*512];
        #pragma unroll
        for (int j = 0; j < 4; j++) acc[j] += cS[(bg*4+j)*512+d]*w;
    }
    float bb = bv[e*512 + h*64 + c];
    #pragma unroll
    for (int j = 0; j < 4; j++){
        int b = bg*4+j;
        g_attn[(b*8+e)*512 + h*64 + c] = acc[j] + bb;
    }
}

// ---------------- k8: x = query + attn @ Wo + bo ----------------
__global__ void k_out(const float* __restrict__ Wo, const float* __restrict__ bo,
                      const float* __restrict__ q){
    int e = blockIdx.x >> 2, kt = blockIdx.x & 3;
    int t = threadIdx.x;
    __shared__ float aS[8192];
    for (int i = t; i < 8192; i += 256){
        int b = i >> 9, d = i & 511;
        aS[i] = g_attn[(b*8+e)*512+d];
    }
    __syncthreads();
    int col = kt*128 + (t & 127), bg = t >> 7;
    float acc[8] = {0,0,0,0,0,0,0,0};
    const float* W = Wo + e*262144 + col;
    for (int d = 0; d < 512; d++){
        float w = W[d*512];
        #pragma unroll
        for (int j = 0; j < 8; j++) acc[j] += aS[(bg*8+j)*512+d]*w;
    }
    float bb = bo[e*512+col];
    #pragma unroll
    for (int j = 0; j < 8; j++){
        int b = bg*8+j;
        g_x[(b*8+e)*512+col] = q[b*512+col] + acc[j] + bb;
    }
}

// ---------------- k9: LN(x) per (b,e) ----------------
__global__ void k_ln(const float* __restrict__ g, const float* __restrict__ be){
    int b = blockIdx.x >> 3, e = blockIdx.x & 7;
    int t = threadIdx.x;
    __shared__ float red[256];
    const float* x = &g_x[(b*8+e)*512];
    float s = 0.f;
    for (int d = t; d < 512; d += 256) s += x[d];
    float mu = blockReduceSum(s, red) * (1.f/512.f);
    float v = 0.f;
    for (int d = t; d < 512; d += 256){ float y = x[d]-mu; v += y*y; }
    float var = blockReduceSum(v, red) * (1.f/512.f);
    float rs = rsqrtf(var + 1e-5f);
    for (int d = t; d < 512; d += 256)
        g_xo[(b*8+e)*512+d] = (x[d]-mu)*rs*g[e*512+d] + be[e*512+d];
}

// ---------------- k10: h1 = gelu(xo @ W1 + b1), exact gelu ----------------
__global__ void k_ffn1(const float* __restrict__ W1, const float* __restrict__ b1){
    int e = blockIdx.x >> 4, ft = blockIdx.x & 15;
    int t = threadIdx.x;
    __shared__ float xS[8192];
    for (int i = t; i < 8192; i += 256){
        int b = i >> 9, d = i & 511;
        xS[i] = g_xo[(b*8+e)*512+d];
    }
    __syncthreads();
    int f = ft*128 + (t & 127), bg = t >> 7;
    float acc[8] = {0,0,0,0,0,0,0,0};
    const float* W = W1 + e*(512*2048) + f;
    for (int d = 0; d < 512; d++){
        float w = W[(long)d*2048];
        #pragma unroll
        for (int j = 0; j < 8; j++) acc[j] += xS[(bg*8+j)*512+d]*w;
    }
    float bb = b1[e*2048+f];
    #pragma unroll
    for (int j = 0; j < 8; j++){
        float v = acc[j] + bb;
        float gl = 0.5f*v*(1.f + erff(v*0.70710678118654752f));
        g_h1[((bg*8+j)*8+e)*2048 + f] = gl;
    }
}

// ---------------- k11: y = h1 @ W2 + b2 + x  (writes straight into d_out y-region) ----------------
__global__ void k_ffn2(const float* __restrict__ W2, const float* __restrict__ b2,
                       float* __restrict__ out_y){
    int e = blockIdx.x >> 3, kt = blockIdx.x & 7;
    int t = threadIdx.x;
    int k = kt*64 + (t & 63), bg = t >> 6;
    __shared__ float hS[16*128];
    float acc[4] = {0,0,0,0};
    for (int fc = 0; fc < 16; fc++){
        __syncthreads();
        for (int i = t; i < 2048; i += 256){
            int b = i >> 7, ff = i & 127;
            hS[i] = g_h1[(b*8+e)*2048 + fc*128 + ff];
        }
        __syncthreads();
        const float* W = W2 + e*(2048*512) + (fc*128)*512 + k;
        for (int ff = 0; ff < 128; ff++){
            float w = W[ff*512];
            #pragma unroll
            for (int j = 0; j < 4; j++) acc[j] += hS[(bg*4+j)*128+ff]*w;
        }
    }
    float bb = b2[e*512+k];
    #pragma unroll
    for (int j = 0; j < 4; j++){
        int b = bg*4+j;
        out_y[(b*8+e)*512+k] = acc[j] + bb + g_x[(b*8+e)*512+k];
    }
}

// ---------------- k12: gt normalization + mixture (ALPHA=1 -> fused = mixture) ----------------
__global__ void k_final(const float* __restrict__ y, float* __restrict__ out){
    int b = blockIdx.x, t = threadIdx.x;
    __shared__ float gt[8];
    if (t == 0){
        float s = 0.f, r[8];
        #pragma unroll
        for (int e = 0; e < 8; e++){ r[e] = g_rel[b*8+e]; s += r[e]; }
        float inv = 1.f/(s + 1e-9f);
        #pragma unroll
        for (int e = 0; e < 8; e++){
            gt[e] = r[e]*inv;
            out[73728 + b*8 + e] = gt[e];
        }
    }
    __syncthreads();
    for (int k = t; k < 512; k += 256){
        float m = 0.f;
        #pragma unroll
        for (int e = 0; e < 8; e++) m += gt[e]*y[(b*8+e)*512+k];
        out[b*512+k] = m;
    }
}

extern "C" void kernel_launch(void* const* d_in, const int* in_sizes, int n_in,
                              void* d_out, int out_size){
    const float* query     = (const float*)d_in[0];
    const float* retrieved = (const float*)d_in[1];
    const float* w_gate    = (const float*)d_in[2];
    const float* ln_q_g    = (const float*)d_in[3];
    const float* ln_q_b    = (const float*)d_in[4];
    const float* Wq        = (const float*)d_in[5];
    const float* bq        = (const float*)d_in[6];
    const float* Wk        = (const float*)d_in[7];
    // d_in[8] = bk: provably unused (softmax shift-invariance drops it)
    const float* Wv        = (const float*)d_in[9];
    const float* bv        = (const float*)d_in[10];
    const float* Wo        = (const float*)d_in[11];
    const float* bo        = (const float*)d_in[12];
    const float* ln_o_g    = (const float*)d_in[13];
    const float* ln_o_b    = (const float*)d_in[14];
    const float* W1        = (const float*)d_in[15];
    const float* b1        = (const float*)d_in[16];
    const float* W2        = (const float*)d_in[17];
    const float* b2        = (const float*)d_in[18];
    float* out = (float*)d_out;

    k_prep  <<<16, 256>>>(query, w_gate);
    k_qh    <<<32, 256>>>(Wq, bq, ln_q_g, ln_q_b);
    k_wt    <<<64, 256>>>(Wk);
    k_scores<<<256,256>>>(retrieved);
    k_soft  <<<128,256>>>();
    k_ctx   <<<256,256>>>(retrieved);
    k_attn  <<<64, 256>>>(Wv, bv);
    k_out   <<<32, 256>>>(Wo, bo, query);
    k_ln    <<<128,256>>>(ln_o_g, ln_o_b);
    k_ffn1  <<<128,256>>>(W1, b1);
    k_ffn2  <<<64, 256>>>(W2, b2, out + 8192);
    k_final <<<16, 256>>>(out + 8192, out);
}

// round 2
// speedup vs baseline: 1.3329x; 1.3329x over previous
#include <cuda_runtime.h>
#include <cuda_bf16.h>
#include <math.h>
#include <stdint.h>

#define B_  16
#define L_  2048
#define D_  512
#define E_  8
#define H_  8
#define EH_ 64
#define F_  2048

typedef unsigned long long ull;

// ---------------- scratch ----------------
__device__ __align__(16) float g_xn[B_*D_];
__device__ __align__(16) float g_gates[B_*E_];
__device__ __align__(16) float g_qh[B_*E_*D_];
__device__ __align__(16) __nv_bfloat16 g_wtb[B_*EH_*D_];     // bf16 folded q.Wk^T / 8
__device__ __align__(16) __nv_bfloat16 g_rb [B_*L_*D_];      // retrieved bf16 [b][l][d]
__device__ __align__(16) __nv_bfloat16 g_rbT[B_*D_*L_];      // retrieved bf16 [b][d][l]
__device__ __align__(16) float g_e[B_*EH_*L_];               // exp(scores)
__device__ __align__(16) __nv_bfloat16 g_pb[B_*EH_*L_];      // probs bf16
__device__ __align__(16) float g_ctx[B_*EH_*D_];
__device__ __align__(16) float g_attn[B_*E_*D_];
__device__ __align__(16) float g_x[B_*E_*D_];
__device__ __align__(16) float g_xo[B_*E_*D_];
__device__ __align__(16) float g_h1[B_*E_*F_];
__device__ __align__(16) float g_yp[4][B_*E_*D_];
__device__ __align__(16) float g_rel[B_*E_];

__device__ __forceinline__ void mma16816(float* c, const uint32_t* a, const uint32_t* b){
    asm volatile(
        "mma.sync.aligned.m16n8k16.row.col.f32.bf16.bf16.f32 "
        "{%0,%1,%2,%3},{%4,%5,%6,%7},{%8,%9},{%0,%1,%2,%3};"
        : "+f"(c[0]), "+f"(c[1]), "+f"(c[2]), "+f"(c[3])
        : "r"(a[0]), "r"(a[1]), "r"(a[2]), "r"(a[3]), "r"(b[0]), "r"(b[1]));
}

__device__ __forceinline__ float blockReduceSum(float v, float* red){
    int t = threadIdx.x;
    red[t] = v; __syncthreads();
    #pragma unroll
    for (int s = 128; s > 0; s >>= 1){ if (t < s) red[t] += red[t+s]; __syncthreads(); }
    float r = red[0]; __syncthreads(); return r;
}

// ---------------- k_prep: query LN stats + gating softmax ----------------
__global__ void k_prep(const float* __restrict__ q, const float* __restrict__ wg){
    int b = blockIdx.x, t = threadIdx.x;
    __shared__ float red[256];
    __shared__ float slog[8];
    float s = 0.f;
    for (int d = t; d < D_; d += 256) s += q[b*D_+d];
    float mu = blockReduceSum(s, red) * (1.f/512.f);
    float v = 0.f;
    for (int d = t; d < D_; d += 256){ float x = q[b*D_+d]-mu; v += x*x; }
    float var = blockReduceSum(v, red) * (1.f/512.f);
    float rs = rsqrtf(var + 1e-5f);
    for (int d = t; d < D_; d += 256) g_xn[b*D_+d] = (q[b*D_+d]-mu)*rs;
    int w = t >> 5, lane = t & 31;
    float p = 0.f;
    for (int d = lane; d < D_; d += 32) p += q[b*D_+d] * wg[d*E_ + w];
    #pragma unroll
    for (int o = 16; o > 0; o >>= 1) p += __shfl_xor_sync(0xffffffffu, p, o);
    if (lane == 0) slog[w] = p;
    __syncthreads();
    if (t == 0){
        float m = slog[0];
        #pragma unroll
        for (int e = 1; e < 8; e++) m = fmaxf(m, slog[e]);
        float z = 0.f, ex[8];
        #pragma unroll
        for (int e = 0; e < 8; e++){ ex[e] = expf(slog[e]-m); z += ex[e]; }
        float iz = 1.f/z;
        #pragma unroll
        for (int e = 0; e < 8; e++) g_gates[b*8+e] = ex[e]*iz;
    }
}

// ---------------- k_conv: retrieved fp32 -> bf16 (row-major + transposed) ----------------
__global__ void k_conv(const float* __restrict__ R){
    int bx = blockIdx.x;
    int b = bx >> 8, lt = (bx >> 3) & 31, dt = bx & 7;
    int l0 = lt*64, d0 = dt*64;
    int t = threadIdx.x;
    __shared__ __nv_bfloat16 s[64][68];
    int ll = t >> 4, dd4 = (t & 15) * 4;
    #pragma unroll
    for (int i = 0; i < 4; i++){
        int l = ll + i*16;
        float4 v = *(const float4*)&R[((size_t)(b*2048)+(l0+l))*512 + d0 + dd4];
        __nv_bfloat162 p0 = __floats2bfloat162_rn(v.x, v.y);
        __nv_bfloat162 p1 = __floats2bfloat162_rn(v.z, v.w);
        uint2 pk; pk.x = *(uint32_t*)&p0; pk.y = *(uint32_t*)&p1;
        *(uint2*)&g_rb[((size_t)(b*2048)+(l0+l))*512 + d0 + dd4] = pk;
        *(uint2*)&s[l][dd4] = pk;
    }
    __syncthreads();
    int w = t >> 5, lane = t & 31;
    int l = lane*2;
    #pragma unroll
    for (int j = 0; j < 8; j++){
        int dd = w*8 + j;
        __nv_bfloat162 pk;
        pk.x = s[l][dd]; pk.y = s[l+1][dd];
        *(uint32_t*)&g_rbT[((size_t)(b*512)+(d0+dd))*2048 + l0 + l] = *(uint32_t*)&pk;
    }
}

// ---------------- k_qh: qh = (xn*g+b) @ Wq + bq ----------------
__global__ void k_qh(const float* __restrict__ Wq, const float* __restrict__ bq,
                     const float* __restrict__ lng, const float* __restrict__ lnb){
    int e = blockIdx.x >> 2, kt = blockIdx.x & 3;
    int t = threadIdx.x;
    __shared__ float sQ[16*512];
    for (int i = t; i < 8192; i += 256){
        int b = i >> 9, d = i & 511;
        sQ[i] = g_xn[b*512+d]*lng[e*512+d] + lnb[e*512+d];
    }
    __syncthreads();
    int col = kt*128 + (t & 127);
    int bg = t >> 7;
    float acc[8] = {0,0,0,0,0,0,0,0};
    const float* W = Wq + e*262144 + col;
    for (int d = 0; d < 512; d++){
        float w = W[d*512];
        #pragma unroll
        for (int j = 0; j < 8; j++) acc[j] += sQ[(bg*8+j)*512+d]*w;
    }
    float bb = bq[e*512+col];
    #pragma unroll
    for (int j = 0; j < 8; j++){
        int b = bg*8+j;
        g_qh[(b*8+e)*512+col] = acc[j] + bb;
    }
}

// ---------------- k_wt: w_tilde -> bf16 ----------------
__global__ void k_wt(const float* __restrict__ Wk){
    int e = blockIdx.x >> 3, dt = blockIdx.x & 7;
    int din0 = dt*64;
    int t = threadIdx.x;
    __shared__ float qhS[16*64];
    __shared__ float wkS[64*65];
    int r = t & 63, bg = t >> 6;
    for (int h = 0; h < 8; h++){
        __syncthreads();
        for (int i = t; i < 1024; i += 256){
            int b = i >> 6, c = i & 63;
            qhS[i] = g_qh[(b*8+e)*512 + h*64 + c];
        }
        for (int i = t; i < 4096; i += 256){
            int rr = i >> 6, c = i & 63;
            wkS[rr*65+c] = Wk[e*262144 + (din0+rr)*512 + h*64 + c];
        }
        __syncthreads();
        #pragma unroll
        for (int j = 0; j < 4; j++){
            int b = bg*4 + j;
            float a = 0.f;
            const float* qp = &qhS[b*64];
            const float* wp = &wkS[r*65];
            #pragma unroll 8
            for (int c = 0; c < 64; c++) a += qp[c]*wp[c];
            g_wtb[((b*64) + (e*8+h))*512 + din0 + r] = __float2bfloat16(a * 0.125f);
        }
    }
}

// ---------------- k_scores: e = exp(r @ wt^T) via bf16 HMMA ----------------
// M = eh (64), N = l (128/block), K = d (512). A=wtb row-major, B=rb col-major.
__global__ void k_scores(){
    int b = blockIdx.x >> 4, lt = blockIdx.x & 15;
    int t = threadIdx.x;
    int w = t >> 5, lane = t & 31;
    int group = lane >> 2, tid4 = lane & 3;
    int eh0 = (w & 3) * 16;
    int l0 = lt*128 + (w >> 2) * 64;
    const __nv_bfloat16* A = g_wtb + (size_t)(b*64 + eh0)*512;
    const __nv_bfloat16* Bp = g_rb + (size_t)(b*2048 + l0)*512;
    float acc[8][4];
    #pragma unroll
    for (int i = 0; i < 8; i++){ acc[i][0]=0.f; acc[i][1]=0.f; acc[i][2]=0.f; acc[i][3]=0.f; }

    for (int ks = 0; ks < 32; ks++){
        int d0 = ks*16;
        uint32_t a[4];
        a[0] = *(const uint32_t*)(A + (size_t)group*512     + d0 + tid4*2);
        a[1] = *(const uint32_t*)(A + (size_t)(group+8)*512 + d0 + tid4*2);
        a[2] = *(const uint32_t*)(A + (size_t)group*512     + d0 + 8 + tid4*2);
        a[3] = *(const uint32_t*)(A + (size_t)(group+8)*512 + d0 + 8 + tid4*2);
        #pragma unroll
        for (int nt = 0; nt < 8; nt++){
            const __nv_bfloat16* bp = Bp + (size_t)(nt*8+group)*512 + d0 + tid4*2;
            uint32_t bb[2];
            bb[0] = *(const uint32_t*)bp;
            bb[1] = *(const uint32_t*)(bp + 8);
            mma16816(acc[nt], a, bb);
        }
    }
    #pragma unroll
    for (int nt = 0; nt < 8; nt++){
        int l = l0 + nt*8 + tid4*2;
        float2 e01 = make_float2(__expf(acc[nt][0]), __expf(acc[nt][1]));
        float2 e23 = make_float2(__expf(acc[nt][2]), __expf(acc[nt][3]));
        *(float2*)&g_e[(size_t)(b*64 + eh0+group)*2048 + l]   = e01;
        *(float2*)&g_e[(size_t)(b*64 + eh0+group+8)*2048 + l] = e23;
    }
}

// ---------------- k_soft: normalize, probs bf16, entropy -> rel ----------------
__global__ void k_soft(){
    int b = blockIdx.x >> 3, e = blockIdx.x & 7;
    int t = threadIdx.x, w = t >> 5, lane = t & 31;
    __shared__ float izs[8];
    __shared__ float red[256];
    const float* rowbase = g_e + (size_t)((b*64)+(e*8))*2048;
    {
        const float* row = rowbase + (size_t)w*2048;
        float z = 0.f;
        for (int l = lane; l < 2048; l += 32) z += row[l];
        #pragma unroll
        for (int o = 16; o > 0; o >>= 1) z += __shfl_xor_sync(0xffffffffu, z, o);
        if (lane == 0) izs[w] = 1.f/z;
    }
    __syncthreads();
    float izl[8];
    #pragma unroll
    for (int h = 0; h < 8; h++) izl[h] = izs[h];
    float ent = 0.f;
    __nv_bfloat16* pbase = g_pb + (size_t)((b*64)+(e*8))*2048;
    for (int l = t; l < 2048; l += 256){
        float pbar = 0.f;
        #pragma unroll
        for (int h = 0; h < 8; h++){
            float p = rowbase[(size_t)h*2048 + l] * izl[h];
            pbase[(size_t)h*2048 + l] = __float2bfloat16(p);
            pbar += p;
        }
        pbar *= 0.125f;
        ent -= pbar * __logf(fmaxf(pbar, 1e-12f));
    }
    float Hn = blockReduceSum(ent, red);
    if (t == 0){
        float sa = __expf(-0.5f*Hn);
        g_rel[b*8+e] = g_gates[b*8+e]*sa;
    }
}

// ---------------- k_ctx: ctx = probs @ r via bf16 HMMA ----------------
// M = eh (64), N = d (64/block), K = l (2048). A=pb row-major, B=rbT col-major.
__global__ void k_ctx(){
    int b = blockIdx.x >> 3, dt = blockIdx.x & 7;
    int t = threadIdx.x;
    int w = t >> 5, lane = t & 31;
    int group = lane >> 2, tid4 = lane & 3;
    int eh0 = (w & 3) * 16;
    int d0w = dt*64 + (w >> 2) * 32;
    const __nv_bfloat16* A = g_pb + (size_t)(b*64 + eh0)*2048;
    const __nv_bfloat16* Bp = g_rbT + (size_t)(b*512 + d0w)*2048;
    float acc[4][4];
    #pragma unroll
    for (int i = 0; i < 4; i++){ acc[i][0]=0.f; acc[i][1]=0.f; acc[i][2]=0.f; acc[i][3]=0.f; }

    for (int ks = 0; ks < 128; ks++){
        int l0 = ks*16;
        uint32_t a[4];
        a[0] = *(const uint32_t*)(A + (size_t)group*2048     + l0 + tid4*2);
        a[1] = *(const uint32_t*)(A + (size_t)(group+8)*2048 + l0 + tid4*2);
        a[2] = *(const uint32_t*)(A + (size_t)group*2048     + l0 + 8 + tid4*2);
        a[3] = *(const uint32_t*)(A + (size_t)(group+8)*2048 + l0 + 8 + tid4*2);
        #pragma unroll
        for (int nt = 0; nt < 4; nt++){
            const __nv_bfloat16* bp = Bp + (size_t)(nt*8+group)*2048 + l0 + tid4*2;
            uint32_t bb[2];
            bb[0] = *(const uint32_t*)bp;
            bb[1] = *(const uint32_t*)(bp + 8);
            mma16816(acc[nt], a, bb);
        }
    }
    #pragma unroll
    for (int nt = 0; nt < 4; nt++){
        int d = d0w + nt*8 + tid4*2;
        *(float2*)&g_ctx[(size_t)(b*64 + eh0+group)*512 + d]   = make_float2(acc[nt][0], acc[nt][1]);
        *(float2*)&g_ctx[(size_t)(b*64 + eh0+group+8)*512 + d] = make_float2(acc[nt][2], acc[nt][3]);
    }
}

// ---------------- k_attn: attn = ctx @ Wv + bv (per head column block) ----------------
__global__ void k_attn(const float* __restrict__ Wv, const float* __restrict__ bv){
    int e = blockIdx.x >> 3, h = blockIdx.x & 7;
    int t = threadIdx.x;
    __shared__ float cS[16*512];
    for (int i = t; i < 8192; i += 256){
        int b = i >> 9, d = i & 511;
        int row = (b*64) + (e*8+h);
        cS[i] = g_ctx[(size_t)row*512+d];
    }
    __syncthreads();
    int c = t & 63, bg = t >> 6;
    float acc[4] = {0,0,0,0};
    const float* W = Wv + e*262144 + h*64 + c;
    for (int d = 0; d < 512; d++){
        float w = W[d*512];
        #pragma unroll
        for (int j = 0; j < 4; j++) acc[j] += cS[(bg*4+j)*512+d]*w;
    }
    float bb = bv[e*512 + h*64 + c];
    #pragma unroll
    for (int j = 0; j < 4; j++){
        int b = bg*4+j;
        g_attn[(b*8+e)*512 + h*64 + c] = acc[j] + bb;
    }
}

// ---------------- k_out: x = query + attn @ Wo + bo ----------------
__global__ void k_out(const float* __restrict__ Wo, const float* __restrict__ bo,
                      const float* __restrict__ q){
    int e = blockIdx.x >> 2, kt = blockIdx.x & 3;
    int t = threadIdx.x;
    __shared__ float aS[8192];
    for (int i = t; i < 8192; i += 256){
        int b = i >> 9, d = i & 511;
        aS[i] = g_attn[(b*8+e)*512+d];
    }
    __syncthreads();
    int col = kt*128 + (t & 127), bg = t >> 7;
    float acc[8] = {0,0,0,0,0,0,0,0};
    const float* W = Wo + e*262144 + col;
    for (int d = 0; d < 512; d++){
        float w = W[d*512];
        #pragma unroll
        for (int j = 0; j < 8; j++) acc[j] += aS[(bg*8+j)*512+d]*w;
    }
    float bb = bo[e*512+col];
    #pragma unroll
    for (int j = 0; j < 8; j++){
        int b = bg*8+j;
        g_x[(b*8+e)*512+col] = q[b*512+col] + acc[j] + bb;
    }
}

// ---------------- k_ln ----------------
__global__ void k_ln(const float* __restrict__ g, const float* __restrict__ be){
    int b = blockIdx.x >> 3, e = blockIdx.x & 7;
    int t = threadIdx.x;
    __shared__ float red[256];
    const float* x = &g_x[(b*8+e)*512];
    float s = 0.f;
    for (int d = t; d < 512; d += 256) s += x[d];
    float mu = blockReduceSum(s, red) * (1.f/512.f);
    float v = 0.f;
    for (int d = t; d < 512; d += 256){ float y = x[d]-mu; v += y*y; }
    float var = blockReduceSum(v, red) * (1.f/512.f);
    float rs = rsqrtf(var + 1e-5f);
    for (int d = t; d < 512; d += 256)
        g_xo[(b*8+e)*512+d] = (x[d]-mu)*rs*g[e*512+d] + be[e*512+d];
}

// ---------------- k_ffn1: h1 = gelu(xo @ W1 + b1) ----------------
__global__ void k_ffn1(const float* __restrict__ W1, const float* __restrict__ b1){
    int e = blockIdx.x >> 4, ft = blockIdx.x & 15;
    int t = threadIdx.x;
    __shared__ float xS[8192];
    for (int i = t; i < 8192; i += 256){
        int b = i >> 9, d = i & 511;
        xS[i] = g_xo[(b*8+e)*512+d];
    }
    __syncthreads();
    int f = ft*128 + (t & 127), bg = t >> 7;
    float acc[8] = {0,0,0,0,0,0,0,0};
    const float* W = W1 + e*1048576 + f;
    for (int d = 0; d < 512; d++){
        float w = W[d*2048];
        #pragma unroll
        for (int j = 0; j < 8; j++) acc[j] += xS[(bg*8+j)*512+d]*w;
    }
    float bb = b1[e*2048+f];
    #pragma unroll
    for (int j = 0; j < 8; j++){
        float v = acc[j] + bb;
        float gl = 0.5f*v*(1.f + erff(v*0.70710678118654752f));
        g_h1[((bg*8+j)*8+e)*2048 + f] = gl;
    }
}

// ---------------- k_ffn2: partial y (split over f) ----------------
__global__ void k_ffn2(const float* __restrict__ W2){
    int bx = blockIdx.x;
    int fs = bx & 3, ct = (bx >> 2) & 7, e = bx >> 5;
    int t = threadIdx.x;
    int col = ct*64 + (t & 63), bg = t >> 6;
    __shared__ float hS[16*128];
    float acc[4] = {0,0,0,0};
    for (int fc = 0; fc < 4; fc++){
        int f0 = fs*512 + fc*128;
        __syncthreads();
        for (int i = t; i < 2048; i += 256){
            int b = i >> 7, ff = i & 127;
            hS[i] = g_h1[(b*8+e)*2048 + f0 + ff];
        }
        __syncthreads();
        const float* W = W2 + e*1048576 + f0*512 + col;
        for (int ff = 0; ff < 128; ff++){
            float w = W[ff*512];
            #pragma unroll
            for (int j = 0; j < 4; j++) acc[j] += hS[(bg*4+j)*128+ff]*w;
        }
    }
    #pragma unroll
    for (int j = 0; j < 4; j++){
        int b = bg*4+j;
        g_yp[fs][(b*8+e)*512+col] = acc[j];
    }
}

// ---------------- k_red: y = sum partials + b2 + x ----------------
__global__ void k_red(const float* __restrict__ b2, float* __restrict__ out_y){
    int idx = blockIdx.x*256 + threadIdx.x;
    float s = g_yp[0][idx] + g_yp[1][idx] + g_yp[2][idx] + g_yp[3][idx];
    int e = (idx >> 9) & 7, k = idx & 511;
    out_y[idx] = s + b2[e*512+k] + g_x[idx];
}

// ---------------- k_final: gt + mixture ----------------
__global__ void k_final(const float* __restrict__ y, float* __restrict__ out){
    int b = blockIdx.x, t = threadIdx.x;
    __shared__ float gt[8];
    if (t == 0){
        float s = 0.f, r[8];
        #pragma unroll
        for (int e = 0; e < 8; e++){ r[e] = g_rel[b*8+e]; s += r[e]; }
        float inv = 1.f/(s + 1e-9f);
        #pragma unroll
        for (int e = 0; e < 8; e++){
            gt[e] = r[e]*inv;
            out[73728 + b*8 + e] = gt[e];
        }
    }
    __syncthreads();
    for (int k = t; k < 512; k += 256){
        float m = 0.f;
        #pragma unroll
        for (int e = 0; e < 8; e++) m += gt[e]*y[(b*8+e)*512+k];
        out[b*512+k] = m;
    }
}

extern "C" void kernel_launch(void* const* d_in, const int* in_sizes, int n_in,
                              void* d_out, int out_size){
    const float* query     = (const float*)d_in[0];
    const float* retrieved = (const float*)d_in[1];
    const float* w_gate    = (const float*)d_in[2];
    const float* ln_q_g    = (const float*)d_in[3];
    const float* ln_q_b    = (const float*)d_in[4];
    const float* Wq        = (const float*)d_in[5];
    const float* bq        = (const float*)d_in[6];
    const float* Wk        = (const float*)d_in[7];
    // d_in[8] = bk: unused (softmax shift invariance)
    const float* Wv        = (const float*)d_in[9];
    const float* bv        = (const float*)d_in[10];
    const float* Wo        = (const float*)d_in[11];
    const float* bo        = (const float*)d_in[12];
    const float* ln_o_g    = (const float*)d_in[13];
    const float* ln_o_b    = (const float*)d_in[14];
    const float* W1        = (const float*)d_in[15];
    const float* b1        = (const float*)d_in[16];
    const float* W2        = (const float*)d_in[17];
    const float* b2        = (const float*)d_in[18];
    float* out = (float*)d_out;

    k_prep  <<<16,  256>>>(query, w_gate);
    k_conv  <<<4096,256>>>(retrieved);
    k_qh    <<<32,  256>>>(Wq, bq, ln_q_g, ln_q_b);
    k_wt    <<<64,  256>>>(Wk);
    k_scores<<<256, 256>>>();
    k_soft  <<<128, 256>>>();
    k_ctx   <<<128, 256>>>();
    k_attn  <<<64,  256>>>(Wv, bv);
    k_out   <<<32,  256>>>(Wo, bo, query);
    k_ln    <<<128, 256>>>(ln_o_g, ln_o_b);
    k_ffn1  <<<128, 256>>>(W1, b1);
    k_ffn2  <<<256, 256>>>(W2);
    k_red   <<<256, 256>>>(b2, out + 8192);
    k_final <<<16,  256>>>(out + 8192, out);
}

// round 5
// speedup vs baseline: 2.6012x; 1.9515x over previous
#include <cuda_runtime.h>
#include <cuda_bf16.h>
#include <math.h>
#include <stdint.h>

#define B_  16
#define L_  2048
#define D_  512
#define E_  8
#define H_  8
#define EH_ 64
#define F_  2048

typedef unsigned long long ull;

// ---------------- scratch ----------------
__device__ __align__(16) float g_xn[B_*D_];
__device__ __align__(16) float g_gates[B_*E_];
__device__ __align__(16) float g_qh[B_*E_*D_];
__device__ __align__(16) __nv_bfloat16 g_wtb[B_*EH_*D_];
__device__ __align__(16) __nv_bfloat16 g_rb [B_*L_*D_];
__device__ __align__(16) __nv_bfloat16 g_rbT[B_*D_*L_];
__device__ __align__(16) float g_e[B_*EH_*L_];
__device__ __align__(16) __nv_bfloat16 g_pb[B_*EH_*L_];
__device__ __align__(16) float g_ctx[B_*EH_*D_];
__device__ __align__(16) float g_attn[B_*E_*D_];
__device__ __align__(16) float g_x[B_*E_*D_];
__device__ __align__(16) float g_xo[B_*E_*D_];
__device__ __align__(16) float g_h1[B_*E_*F_];
__device__ __align__(16) float g_yp[4][B_*E_*D_];
__device__ __align__(16) float g_rel[B_*E_];

__device__ __forceinline__ void mma16816(float* c, const uint32_t* a, const uint32_t* b){
    asm volatile(
        "mma.sync.aligned.m16n8k16.row.col.f32.bf16.bf16.f32 "
        "{%0,%1,%2,%3},{%4,%5,%6,%7},{%8,%9},{%0,%1,%2,%3};"
        : "+f"(c[0]), "+f"(c[1]), "+f"(c[2]), "+f"(c[3])
        : "r"(a[0]), "r"(a[1]), "r"(a[2]), "r"(a[3]), "r"(b[0]), "r"(b[1]));
}

__device__ __forceinline__ float blockReduceSum(float v, float* red){
    int t = threadIdx.x;
    red[t] = v; __syncthreads();
    #pragma unroll
    for (int s = 128; s > 0; s >>= 1){ if (t < s) red[t] += red[t+s]; __syncthreads(); }
    float r = red[0]; __syncthreads(); return r;
}

// ---------------- k_prep ----------------
__global__ void k_prep(const float* __restrict__ q, const float* __restrict__ wg){
    int b = blockIdx.x, t = threadIdx.x;
    __shared__ float red[256];
    __shared__ float slog[8];
    float s = 0.f;
    for (int d = t; d < D_; d += 256) s += q[b*D_+d];
    float mu = blockReduceSum(s, red) * (1.f/512.f);
    float v = 0.f;
    for (int d = t; d < D_; d += 256){ float x = q[b*D_+d]-mu; v += x*x; }
    float var = blockReduceSum(v, red) * (1.f/512.f);
    float rs = rsqrtf(var + 1e-5f);
    for (int d = t; d < D_; d += 256) g_xn[b*D_+d] = (q[b*D_+d]-mu)*rs;
    int w = t >> 5, lane = t & 31;
    float p = 0.f;
    for (int d = lane; d < D_; d += 32) p += q[b*D_+d] * wg[d*E_ + w];
    #pragma unroll
    for (int o = 16; o > 0; o >>= 1) p += __shfl_xor_sync(0xffffffffu, p, o);
    if (lane == 0) slog[w] = p;
    __syncthreads();
    if (t == 0){
        float m = slog[0];
        #pragma unroll
        for (int e = 1; e < 8; e++) m = fmaxf(m, slog[e]);
        float z = 0.f, ex[8];
        #pragma unroll
        for (int e = 0; e < 8; e++){ ex[e] = expf(slog[e]-m); z += ex[e]; }
        float iz = 1.f/z;
        #pragma unroll
        for (int e = 0; e < 8; e++) g_gates[b*8+e] = ex[e]*iz;
    }
}

// ---------------- k_conv: retrieved fp32 -> bf16 row + transposed ----------------
__global__ void k_conv(const float* __restrict__ R){
    int bx = blockIdx.x;
    int b = bx >> 8, lt = (bx >> 3) & 31, dt = bx & 7;
    int l0 = lt*64, d0 = dt*64;
    int t = threadIdx.x;
    __shared__ __nv_bfloat16 s[64][68];
    int ll = t >> 4, dd4 = (t & 15) * 4;
    #pragma unroll
    for (int i = 0; i < 4; i++){
        int l = ll + i*16;
        float4 v = *(const float4*)&R[((size_t)(b*2048)+(l0+l))*512 + d0 + dd4];
        __nv_bfloat162 p0 = __floats2bfloat162_rn(v.x, v.y);
        __nv_bfloat162 p1 = __floats2bfloat162_rn(v.z, v.w);
        uint2 pk; pk.x = *(uint32_t*)&p0; pk.y = *(uint32_t*)&p1;
        *(uint2*)&g_rb[((size_t)(b*2048)+(l0+l))*512 + d0 + dd4] = pk;
        *(uint2*)&s[l][dd4] = pk;
    }
    __syncthreads();
    int w = t >> 5, lane = t & 31;
    int l = lane*2;
    #pragma unroll
    for (int j = 0; j < 8; j++){
        int dd = w*8 + j;
        __nv_bfloat162 pk;
        pk.x = s[l][dd]; pk.y = s[l+1][dd];
        *(uint32_t*)&g_rbT[((size_t)(b*512)+(d0+dd))*2048 + l0 + l] = *(uint32_t*)&pk;
    }
}

// ======== unified streaming weight-GEMM pattern:
// 256 threads = 64 cols x 4 kgroups; act tile 16x512 in smem; padded smem reduce.

// ---------------- k_qh: qh = (xn*g+b) @ Wq + bq ----------------
__global__ void k_qh(const float* __restrict__ Wq, const float* __restrict__ bq,
                     const float* __restrict__ lng, const float* __restrict__ lnb){
    int e = blockIdx.x >> 3, ct = blockIdx.x & 7;
    int t = threadIdx.x;
    __shared__ float actS[16*512];
    for (int i = t; i < 8192; i += 256){
        int b = i >> 9, d = i & 511;
        actS[i] = g_xn[b*512+d]*lng[e*512+d] + lnb[e*512+d];
    }
    __syncthreads();
    int cl = t & 63, kg = t >> 6;
    int col = ct*64 + cl;
    const float* W = Wq + e*262144 + (kg*128)*512 + col;
    const float* a = actS + kg*128;
    float acc[16];
    #pragma unroll
    for (int b = 0; b < 16; b++) acc[b] = 0.f;
    #pragma unroll 4
    for (int kk = 0; kk < 128; kk++){
        float w = W[kk*512];
        #pragma unroll
        for (int b = 0; b < 16; b++) acc[b] += a[b*512+kk]*w;
    }
    __syncthreads();
    float* red = actS;
    #pragma unroll
    for (int b = 0; b < 16; b++) red[(b*4+kg)*64 + cl] = acc[b];
    __syncthreads();
    #pragma unroll
    for (int j = 0; j < 4; j++){
        int b = kg*4+j;
        float s = red[(b*4+0)*64+cl] + red[(b*4+1)*64+cl]
                + red[(b*4+2)*64+cl] + red[(b*4+3)*64+cl];
        g_qh[(b*8+e)*512+col] = s + bq[e*512+col];
    }
}

// ---------------- k_wt: wt[b,e*8+h,din] = (qh_h . Wk[din]_h)/8 -> bf16 ----------------
__global__ void k_wt(const float* __restrict__ Wk){
    int bx = blockIdx.x;
    int e = bx >> 4, h = (bx >> 1) & 7, dg = bx & 1;
    int t = threadIdx.x;
    int din = dg*256 + t;
    __shared__ float qhS[16*64];
    for (int i = t; i < 1024; i += 256){
        int b = i >> 6, c = i & 63;
        qhS[i] = g_qh[(b*8+e)*512 + h*64 + c];
    }
    __syncthreads();
    const float4* W = (const float4*)(Wk + e*262144 + din*512 + h*64);
    float acc[16];
    #pragma unroll
    for (int b = 0; b < 16; b++) acc[b] = 0.f;
    #pragma unroll 4
    for (int q4 = 0; q4 < 16; q4++){
        float4 w = W[q4];
        int c = q4*4;
        #pragma unroll
        for (int b = 0; b < 16; b++){
            acc[b] += qhS[b*64+c]*w.x + qhS[b*64+c+1]*w.y
                    + qhS[b*64+c+2]*w.z + qhS[b*64+c+3]*w.w;
        }
    }
    #pragma unroll
    for (int b = 0; b < 16; b++)
        g_wtb[(b*64 + e*8 + h)*512 + din] = __float2bfloat16(acc[b]*0.125f);
}

// ---------------- k_scores: e = exp(r @ wt^T) via bf16 HMMA ----------------
__global__ void k_scores(){
    int b = blockIdx.x >> 4, lt = blockIdx.x & 15;
    int t = threadIdx.x;
    int w = t >> 5, lane = t & 31;
    int group = lane >> 2, tid4 = lane & 3;
    int eh0 = (w & 3) * 16;
    int l0 = lt*128 + (w >> 2) * 64;
    const __nv_bfloat16* A = g_wtb + (size_t)(b*64 + eh0)*512;
    const __nv_bfloat16* Bp = g_rb + (size_t)(b*2048 + l0)*512;
    float acc[8][4];
    #pragma unroll
    for (int i = 0; i < 8; i++){ acc[i][0]=0.f; acc[i][1]=0.f; acc[i][2]=0.f; acc[i][3]=0.f; }

    for (int ks = 0; ks < 32; ks++){
        int d0 = ks*16;
        uint32_t a[4];
        a[0] = *(const uint32_t*)(A + (size_t)group*512     + d0 + tid4*2);
        a[1] = *(const uint32_t*)(A + (size_t)(group+8)*512 + d0 + tid4*2);
        a[2] = *(const uint32_t*)(A + (size_t)group*512     + d0 + 8 + tid4*2);
        a[3] = *(const uint32_t*)(A + (size_t)(group+8)*512 + d0 + 8 + tid4*2);
        #pragma unroll
        for (int nt = 0; nt < 8; nt++){
            const __nv_bfloat16* bp = Bp + (size_t)(nt*8+group)*512 + d0 + tid4*2;
            uint32_t bb[2];
            bb[0] = *(const uint32_t*)bp;
            bb[1] = *(const uint32_t*)(bp + 8);
            mma16816(acc[nt], a, bb);
        }
    }
    #pragma unroll
    for (int nt = 0; nt < 8; nt++){
        int l = l0 + nt*8 + tid4*2;
        float2 e01 = make_float2(__expf(acc[nt][0]), __expf(acc[nt][1]));
        float2 e23 = make_float2(__expf(acc[nt][2]), __expf(acc[nt][3]));
        *(float2*)&g_e[(size_t)(b*64 + eh0+group)*2048 + l]   = e01;
        *(float2*)&g_e[(size_t)(b*64 + eh0+group+8)*2048 + l] = e23;
    }
}

// ---------------- k_soft ----------------
__global__ void k_soft(){
    int b = blockIdx.x >> 3, e = blockIdx.x & 7;
    int t = threadIdx.x, w = t >> 5, lane = t & 31;
    __shared__ float izs[8];
    __shared__ float red[256];
    const float* rowbase = g_e + (size_t)((b*64)+(e*8))*2048;
    {
        const float* row = rowbase + (size_t)w*2048;
        float z = 0.f;
        for (int l = lane; l < 2048; l += 32) z += row[l];
        #pragma unroll
        for (int o = 16; o > 0; o >>= 1) z += __shfl_xor_sync(0xffffffffu, z, o);
        if (lane == 0) izs[w] = 1.f/z;
    }
    __syncthreads();
    float izl[8];
    #pragma unroll
    for (int h = 0; h < 8; h++) izl[h] = izs[h];
    float ent = 0.f;
    __nv_bfloat16* pbase = g_pb + (size_t)((b*64)+(e*8))*2048;
    for (int l = t; l < 2048; l += 256){
        float pbar = 0.f;
        #pragma unroll
        for (int h = 0; h < 8; h++){
            float p = rowbase[(size_t)h*2048 + l] * izl[h];
            pbase[(size_t)h*2048 + l] = __float2bfloat16(p);
            pbar += p;
        }
        pbar *= 0.125f;
        ent -= pbar * __logf(fmaxf(pbar, 1e-12f));
    }
    float Hn = blockReduceSum(ent, red);
    if (t == 0){
        float sa = __expf(-0.5f*Hn);
        g_rel[b*8+e] = g_gates[b*8+e]*sa;
    }
}

// ---------------- k_ctx: ctx = probs @ r via bf16 HMMA ----------------
__global__ void k_ctx(){
    int b = blockIdx.x >> 3, dt = blockIdx.x & 7;
    int t = threadIdx.x;
    int w = t >> 5, lane = t & 31;
    int group = lane >> 2, tid4 = lane & 3;
    int eh0 = (w & 3) * 16;
    int d0w = dt*64 + (w >> 2) * 32;
    const __nv_bfloat16* A = g_pb + (size_t)(b*64 + eh0)*2048;
    const __nv_bfloat16* Bp = g_rbT + (size_t)(b*512 + d0w)*2048;
    float acc[4][4];
    #pragma unroll
    for (int i = 0; i < 4; i++){ acc[i][0]=0.f; acc[i][1]=0.f; acc[i][2]=0.f; acc[i][3]=0.f; }

    for (int ks = 0; ks < 128; ks++){
        int l0 = ks*16;
        uint32_t a[4];
        a[0] = *(const uint32_t*)(A + (size_t)group*2048     + l0 + tid4*2);
        a[1] = *(const uint32_t*)(A + (size_t)(group+8)*2048 + l0 + tid4*2);
        a[2] = *(const uint32_t*)(A + (size_t)group*2048     + l0 + 8 + tid4*2);
        a[3] = *(const uint32_t*)(A + (size_t)(group+8)*2048 + l0 + 8 + tid4*2);
        #pragma unroll
        for (int nt = 0; nt < 4; nt++){
            const __nv_bfloat16* bp = Bp + (size_t)(nt*8+group)*2048 + l0 + tid4*2;
            uint32_t bb[2];
            bb[0] = *(const uint32_t*)bp;
            bb[1] = *(const uint32_t*)(bp + 8);
            mma16816(acc[nt], a, bb);
        }
    }
    #pragma unroll
    for (int nt = 0; nt < 4; nt++){
        int d = d0w + nt*8 + tid4*2;
        *(float2*)&g_ctx[(size_t)(b*64 + eh0+group)*512 + d]   = make_float2(acc[nt][0], acc[nt][1]);
        *(float2*)&g_ctx[(size_t)(b*64 + eh0+group+8)*512 + d] = make_float2(acc[nt][2], acc[nt][3]);
    }
}

// ---------------- k_attn: attn = ctx @ Wv + bv  (ct == head) ----------------
__global__ void k_attn(const float* __restrict__ Wv, const float* __restrict__ bv){
    int e = blockIdx.x >> 3, ct = blockIdx.x & 7;
    int t = threadIdx.x;
    __shared__ float actS[16*512];
    for (int i = t; i < 8192; i += 256){
        int b = i >> 9, d = i & 511;
        actS[i] = g_ctx[(size_t)(b*64 + e*8 + ct)*512 + d];
    }
    __syncthreads();
    int cl = t & 63, kg = t >> 6;
    int col = ct*64 + cl;
    const float* W = Wv + e*262144 + (kg*128)*512 + col;
    const float* a = actS + kg*128;
    float acc[16];
    #pragma unroll
    for (int b = 0; b < 16; b++) acc[b] = 0.f;
    #pragma unroll 4
    for (int kk = 0; kk < 128; kk++){
        float w = W[kk*512];
        #pragma unroll
        for (int b = 0; b < 16; b++) acc[b] += a[b*512+kk]*w;
    }
    __syncthreads();
    float* red = actS;
    #pragma unroll
    for (int b = 0; b < 16; b++) red[(b*4+kg)*64 + cl] = acc[b];
    __syncthreads();
    #pragma unroll
    for (int j = 0; j < 4; j++){
        int b = kg*4+j;
        float s = red[(b*4+0)*64+cl] + red[(b*4+1)*64+cl]
                + red[(b*4+2)*64+cl] + red[(b*4+3)*64+cl];
        g_attn[(b*8+e)*512+col] = s + bv[e*512+col];
    }
}

// ---------------- k_out: x = query + attn @ Wo + bo ----------------
__global__ void k_out(const float* __restrict__ Wo, const float* __restrict__ bo,
                      const float* __restrict__ q){
    int e = blockIdx.x >> 3, ct = blockIdx.x & 7;
    int t = threadIdx.x;
    __shared__ float actS[16*512];
    for (int i = t; i < 8192; i += 256){
        int b = i >> 9, d = i & 511;
        actS[i] = g_attn[(b*8+e)*512+d];
    }
    __syncthreads();
    int cl = t & 63, kg = t >> 6;
    int col = ct*64 + cl;
    const float* W = Wo + e*262144 + (kg*128)*512 + col;
    const float* a = actS + kg*128;
    float acc[16];
    #pragma unroll
    for (int b = 0; b < 16; b++) acc[b] = 0.f;
    #pragma unroll 4
    for (int kk = 0; kk < 128; kk++){
        float w = W[kk*512];
        #pragma unroll
        for (int b = 0; b < 16; b++) acc[b] += a[b*512+kk]*w;
    }
    __syncthreads();
    float* red = actS;
    #pragma unroll
    for (int b = 0; b < 16; b++) red[(b*4+kg)*64 + cl] = acc[b];
    __syncthreads();
    #pragma unroll
    for (int j = 0; j < 4; j++){
        int b = kg*4+j;
        float s = red[(b*4+0)*64+cl] + red[(b*4+1)*64+cl]
                + red[(b*4+2)*64+cl] + red[(b*4+3)*64+cl];
        g_x[(b*8+e)*512+col] = q[b*512+col] + s + bo[e*512+col];
    }
}

// ---------------- k_ln ----------------
__global__ void k_ln(const float* __restrict__ g, const float* __restrict__ be){
    int b = blockIdx.x >> 3, e = blockIdx.x & 7;
    int t = threadIdx.x;
    __shared__ float red[256];
    const float* x = &g_x[(b*8+e)*512];
    float s = 0.f;
    for (int d = t; d < 512; d += 256) s += x[d];
    float mu = blockReduceSum(s, red) * (1.f/512.f);
    float v = 0.f;
    for (int d = t; d < 512; d += 256){ float y = x[d]-mu; v += y*y; }
    float var = blockReduceSum(v, red) * (1.f/512.f);
    float rs = rsqrtf(var + 1e-5f);
    for (int d = t; d < 512; d += 256)
        g_xo[(b*8+e)*512+d] = (x[d]-mu)*rs*g[e*512+d] + be[e*512+d];
}

// ---------------- k_ffn1: h1 = gelu(xo @ W1 + b1) ----------------
__global__ void k_ffn1(const float* __restrict__ W1, const float* __restrict__ b1){
    int e = blockIdx.x >> 5, ct = blockIdx.x & 31;
    int t = threadIdx.x;
    __shared__ float actS[16*512];
    for (int i = t; i < 8192; i += 256){
        int b = i >> 9, d = i & 511;
        actS[i] = g_xo[(b*8+e)*512+d];
    }
    __syncthreads();
    int cl = t & 63, kg = t >> 6;
    int col = ct*64 + cl;
    const float* W = W1 + e*1048576 + (kg*128)*2048 + col;
    const float* a = actS + kg*128;
    float acc[16];
    #pragma unroll
    for (int b = 0; b < 16; b++) acc[b] = 0.f;
    #pragma unroll 4
    for (int kk = 0; kk < 128; kk++){
        float w = W[kk*2048];
        #pragma unroll
        for (int b = 0; b < 16; b++) acc[b] += a[b*512+kk]*w;
    }
    __syncthreads();
    float* red = actS;
    #pragma unroll
    for (int b = 0; b < 16; b++) red[(b*4+kg)*64 + cl] = acc[b];
    __syncthreads();
    float bb = b1[e*2048+col];
    #pragma unroll
    for (int j = 0; j < 4; j++){
        int b = kg*4+j;
        float s = red[(b*4+0)*64+cl] + red[(b*4+1)*64+cl]
                + red[(b*4+2)*64+cl] + red[(b*4+3)*64+cl];
        float v = s + bb;
        g_h1[(b*8+e)*2048+col] = 0.5f*v*(1.f + erff(v*0.70710678118654752f));
    }
}

// ---------------- k_ffn2: partial y over f-chunks ----------------
__global__ void k_ffn2(const float* __restrict__ W2){
    int bx = blockIdx.x;
    int e = bx >> 5, ct = (bx >> 2) & 7, ks = bx & 3;
    int t = threadIdx.x;
    __shared__ float actS[16*512];
    for (int i = t; i < 8192; i += 256){
        int b = i >> 9, f = i & 511;
        actS[i] = g_h1[(b*8+e)*2048 + ks*512 + f];
    }
    __syncthreads();
    int cl = t & 63, kg = t >> 6;
    int col = ct*64 + cl;
    const float* W = W2 + e*1048576 + (ks*512 + kg*128)*512 + col;
    const float* a = actS + kg*128;
    float acc[16];
    #pragma unroll
    for (int b = 0; b < 16; b++) acc[b] = 0.f;
    #pragma unroll 4
    for (int kk = 0; kk < 128; kk++){
        float w = W[kk*512];
        #pragma unroll
        for (int b = 0; b < 16; b++) acc[b] += a[b*512+kk]*w;
    }
    __syncthreads();
    float* red = actS;
    #pragma unroll
    for (int b = 0; b < 16; b++) red[(b*4+kg)*64 + cl] = acc[b];
    __syncthreads();
    #pragma unroll
    for (int j = 0; j < 4; j++){
        int b = kg*4+j;
        float s = red[(b*4+0)*64+cl] + red[(b*4+1)*64+cl]
                + red[(b*4+2)*64+cl] + red[(b*4+3)*64+cl];
        g_yp[ks][(b*8+e)*512+col] = s;
    }
}

// ---------------- k_red: y = sum partials + b2 + x ----------------
__global__ void k_red(const float* __restrict__ b2, float* __restrict__ out_y){
    int idx = blockIdx.x*256 + threadIdx.x;
    float s = g_yp[0][idx] + g_yp[1][idx] + g_yp[2][idx] + g_yp[3][idx];
    int e = (idx >> 9) & 7, k = idx & 511;
    out_y[idx] = s + b2[e*512+k] + g_x[idx];
}

// ---------------- k_final ----------------
__global__ void k_final(const float* __restrict__ y, float* __restrict__ out){
    int b = blockIdx.x, t = threadIdx.x;
    __shared__ float gt[8];
    if (t == 0){
        float s = 0.f, r[8];
        #pragma unroll
        for (int e = 0; e < 8; e++){ r[e] = g_rel[b*8+e]; s += r[e]; }
        float inv = 1.f/(s + 1e-9f);
        #pragma unroll
        for (int e = 0; e < 8; e++){
            gt[e] = r[e]*inv;
            out[73728 + b*8 + e] = gt[e];
        }
    }
    __syncthreads();
    for (int k = t; k < 512; k += 256){
        float m = 0.f;
        #pragma unroll
        for (int e = 0; e < 8; e++) m += gt[e]*y[(b*8+e)*512+k];
        out[b*512+k] = m;
    }
}

extern "C" void kernel_launch(void* const* d_in, const int* in_sizes, int n_in,
                              void* d_out, int out_size){
    const float* query     = (const float*)d_in[0];
    const float* retrieved = (const float*)d_in[1];
    const float* w_gate    = (const float*)d_in[2];
    const float* ln_q_g    = (const float*)d_in[3];
    const float* ln_q_b    = (const float*)d_in[4];
    const float* Wq        = (const float*)d_in[5];
    const float* bq        = (const float*)d_in[6];
    const float* Wk        = (const float*)d_in[7];
    // d_in[8] = bk: unused (softmax shift invariance)
    const float* Wv        = (const float*)d_in[9];
    const float* bv        = (const float*)d_in[10];
    const float* Wo        = (const float*)d_in[11];
    const float* bo        = (const float*)d_in[12];
    const float* ln_o_g    = (const float*)d_in[13];
    const float* ln_o_b    = (const float*)d_in[14];
    const float* W1        = (const float*)d_in[15];
    const float* b1        = (const float*)d_in[16];
    const float* W2        = (const float*)d_in[17];
    const float* b2        = (const float*)d_in[18];
    float* out = (float*)d_out;

    k_prep  <<<16,  256>>>(query, w_gate);
    k_conv  <<<4096,256>>>(retrieved);
    k_qh    <<<64,  256>>>(Wq, bq, ln_q_g, ln_q_b);
    k_wt    <<<128, 256>>>(Wk);
    k_scores<<<256, 256>>>();
    k_soft  <<<128, 256>>>();
    k_ctx   <<<128, 256>>>();
    k_attn  <<<64,  256>>>(Wv, bv);
    k_out   <<<64,  256>>>(Wo, bo, query);
    k_ln    <<<128, 256>>>(ln_o_g, ln_o_b);
    k_ffn1  <<<256, 256>>>(W1, b1);
    k_ffn2  <<<256, 256>>>(W2);
    k_red   <<<256, 256>>>(b2, out + 8192);
    k_final <<<16,  256>>>(out + 8192, out);
}